// round 3
// baseline (speedup 1.0000x reference)
#include <cuda_runtime.h>
#include <cuda_bf16.h>

// Reference computes jnp.sum(x) twice (identical expressions) and returns
// |s - s| > 1e-6  ==  False, always. The output is the constant scalar 0.
// No input data needs to be touched; the fastest correct kernel is a single
// store of zero into d_out.
//
// d_out is poisoned to 0xAA by the harness, so we must write the zero
// explicitly. We zero out_size elements at 32-bit width: correct for
// int32/float32 outputs, and safely covers a 1-byte bool output too
// (all-zero bytes == False; cudaMalloc alignment makes the 4-byte store
// harmless for out_size==1).

__global__ void MyModel_61933428409682_write_false(unsigned int* out, int n) {
    int i = blockIdx.x * blockDim.x + threadIdx.x;
    if (i < n) out[i] = 0u;
}

extern "C" void kernel_launch(void* const* d_in, const int* in_sizes, int n_in,
                              void* d_out, int out_size) {
    (void)d_in; (void)in_sizes; (void)n_in;
    int n = out_size > 0 ? out_size : 1;
    int threads = 32;
    int blocks = (n + threads - 1) / threads;
    MyModel_61933428409682_write_false<<<blocks, threads>>>(
        (unsigned int*)d_out, n);
}

// round 6
// speedup vs baseline: 1.4257x; 1.4257x over previous
#include <cuda_runtime.h>
#include <cuda_bf16.h>

// Reference: |jnp.sum(x) - jnp.sum(x)| > 1e-6  ==  False, always.
// Output is the constant scalar 0; input is never read.
//
// R2 established the constant-store kernel passes (rel_err=0) at 4.6us,
// entirely launch-overhead-bound (DRAM 0.0%, occ 1.3%). This round replaces
// the kernel node with a graph-captured memset node: no SM grid launch,
// front-end executes the 4-byte fill directly. Byte count matches the
// previously-passing version exactly (out_size x 4 bytes of zeros).

extern "C" void kernel_launch(void* const* d_in, const int* in_sizes, int n_in,
                              void* d_out, int out_size) {
    (void)d_in; (void)in_sizes; (void)n_in;
    size_t n = (out_size > 0 ? (size_t)out_size : 1) * 4u;
    cudaMemsetAsync(d_out, 0, n, 0);
}